// round 9
// baseline (speedup 1.0000x reference)
#include <cuda_runtime.h>
#include <cuda_fp16.h>
#include <math.h>

#define Bb 32
#define Nn 512
#define Mm 512
#define EPSV 0.05f
#define INV_EPS 20.0f
#define SHIFT 10.0f
#define NITERS 50

#define NBLK 128            // 4 blocks per batch, 1 per SM
#define NTHR 1024           // 32 warps, warp owns 4 rows

// Scratch (device globals: allocation-free per harness rules)
__device__ float g_ahat[Bb * Nn];               // normalized masked weights
__device__ float g_bhat[Bb * Mm];
__device__ float g_uhat[Bb * Nn];               // final scaled u' = u*e^{-20dmin-SHIFT}
__device__ float g_dmin[Bb * Nn];               // per-row min valid distance
__device__ float g_mmask[Bb];                   // # masked columns per batch
__device__ float g_Spart[2][Bb][4][Mm];         // column-sum partials (dbl-buffered)
__device__ float g_fpart[Bb * 8];               // final ot partials

// per-batch software barrier
__device__ unsigned g_count[Bb];
__device__ volatile unsigned g_gen[Bb];

// ---------------------------------------------------------------------------
// prep: normalized weights, masked-col count, huber into out[b], barrier reset
__global__ void prep_kernel(const float* __restrict__ a_mask,
                            const float* __restrict__ pc_a,
                            const float* __restrict__ b_mask,
                            const float* __restrict__ pc_b,
                            float* __restrict__ out)
{
    int b = blockIdx.x, t = threadIdx.x;
    if (t == 0) { g_count[b] = 0; g_gen[b] = 0; }

    float apt = a_mask[b * Nn + t] * pc_a[(b * Nn + t) * 3 + 2];
    float bpt = b_mask[b * Mm + t] * pc_b[(b * Mm + t) * 3 + 2];

    __shared__ float ra[512], rb[512];
    ra[t] = apt; rb[t] = bpt;
    __syncthreads();
    for (int o = 256; o; o >>= 1) {
        if (t < o) { ra[t] += ra[t + o]; rb[t] += rb[t + o]; }
        __syncthreads();
    }
    float sa = ra[0], sb = rb[0];
    __syncthreads();

    g_ahat[b * Nn + t] = apt / sa;   // masked -> 0
    g_bhat[b * Mm + t] = bpt / sb;

    // count masked b columns
    ra[t] = (bpt > 0.f) ? 0.f : 1.f;
    __syncthreads();
    for (int o = 256; o; o >>= 1) {
        if (t < o) ra[t] += ra[t + o];
        __syncthreads();
    }
    if (t == 0) {
        g_mmask[b] = ra[0];
        float e = sa - sb;
        float ae = fabsf(e);
        out[b] = (ae <= 1.f) ? 0.5f * e * e : (ae - 0.5f);
    }
}

// ---------------------------------------------------------------------------
// per-batch grid barrier (4 blocks of one batch)
__device__ __forceinline__ void gsync_batch(int b, unsigned target)
{
    __syncthreads();
    if (threadIdx.x == 0) {
        __threadfence();
        unsigned arrived = atomicAdd(&g_count[b], 1u);
        if (arrived == 3u) {
            g_count[b] = 0;
            __threadfence();
            g_gen[b] = target;
        } else {
            while (g_gen[b] < target) { }
        }
    }
    __syncthreads();
}

// ---------------------------------------------------------------------------
// persistent fused Sinkhorn, SMEM-resident fp16 tile with row-max scaling:
//   t_ij = exp((dmin_i - d_ij)*INV_EPS + SHIFT)   (0 for masked pairs)
// grid = NBLK(128), block = NTHR(1024): 32 warps, warp owns 4 rows.
// smem: ev[512] | cpart[32*512] | tile half[128*512]  (194 KB)
__global__ void __launch_bounds__(NTHR, 1) sinkhorn_kernel(
    const float* __restrict__ pc_a, const float* __restrict__ pc_b)
{
    extern __shared__ float smem[];
    float*  ev    = smem;                       // 512 f
    float*  cpart = smem + 512;                 // 32*512 f
    __half* tile  = (__half*)(smem + 512 + 32 * 512);   // 128*512 h

    int batch    = blockIdx.x >> 2;
    int slot     = blockIdx.x & 3;
    int row_base = slot * 128;
    int t = threadIdx.x, w = t >> 5, lane = t & 31;

    // ---- build tile ---- (temporary overlay of pc_b columns in cpart space)
    float* bxs = cpart;
    float* bys = cpart + 512;
    float* bvs = cpart + 1024;
    for (int j = t; j < 512; j += NTHR) {
        int gb = batch * 512 + j;
        bxs[j] = pc_b[gb * 3 + 0];
        bys[j] = pc_b[gb * 3 + 1];
        bvs[j] = g_bhat[gb];                    // >0 iff valid column
    }
    __syncthreads();

    float mmask = g_mmask[batch];
    float scr[4], ahr[4];
#pragma unroll
    for (int r = 0; r < 4; r++) {
        int row  = w * 4 + r;
        int grow = batch * 512 + row_base + row;
        float ax = pc_a[grow * 3 + 0];          // broadcast
        float ay = pc_a[grow * 3 + 1];
        float ah = g_ahat[grow];
        ahr[r] = ah;

        float dv[16];
        float mn = 1e30f;
#pragma unroll
        for (int k = 0; k < 16; k++) {
            int j = k * 32 + lane;
            float dx = ax - bxs[j], dy = ay - bys[j];
            float d  = sqrtf(__fmaf_rn(dx, dx, __fmaf_rn(dy, dy, 1e-12f)));
            dv[k] = d;
            if (bvs[j] > 0.f) mn = fminf(mn, d);
        }
#pragma unroll
        for (int o = 16; o; o >>= 1) mn = fminf(mn, __shfl_xor_sync(0xFFFFFFFFu, mn, o));

        if (lane == 0) g_dmin[grow] = mn;
        scr[r] = __expf(-__fmaf_rn(INV_EPS, mn, SHIFT));   // e^{-20*mn-SHIFT}

#pragma unroll
        for (int k = 0; k < 16; k++) {
            int j = k * 32 + lane;
            float arg = fminf((mn - dv[k]) * INV_EPS, 0.f) + SHIFT;
            float tv  = (bvs[j] > 0.f && ah > 0.f) ? __expf(arg) : 0.f;
            tile[row * 512 + j] = __float2half(tv);
        }
    }

    float bh = (t < 512) ? g_bhat[batch * 512 + t] : 0.f;
    __syncthreads();     // cpart overlay dead; tile per-warp self-owned

    // ---- 50 iterations ----
    for (int it = 0; it < NITERS; ++it) {
        if (t < 512) {
            if (it == 0) {
                ev[t] = 1.f;                    // reference: logv starts at 0
            } else {
                int rb = it & 1;
                float S = __ldcg(&g_Spart[rb][batch][0][t])
                        + __ldcg(&g_Spart[rb][batch][1][t])
                        + __ldcg(&g_Spart[rb][batch][2][t])
                        + __ldcg(&g_Spart[rb][batch][3][t]);
                ev[t] = bh / fmaxf(S, 1e-35f);  // masked: bh=0 -> ev=0
            }
        }
        __syncthreads();

        const float4* ev4 = (const float4*)ev;
        float4 e0 = ev4[lane * 2],      e1 = ev4[lane * 2 + 1];
        float4 e2 = ev4[64 + lane * 2], e3 = ev4[64 + lane * 2 + 1];
        float sv[16] = {e0.x,e0.y,e0.z,e0.w, e1.x,e1.y,e1.z,e1.w,
                        e2.x,e2.y,e2.z,e2.w, e3.x,e3.y,e3.z,e3.w};

        float c[16];
#pragma unroll
        for (int k = 0; k < 16; k++) c[k] = 0.f;

#pragma unroll
        for (int r = 0; r < 4; r++) {
            int row = w * 4 + r;
            const uint4* rp = (const uint4*)(tile + row * 512);
            uint4 q0 = rp[lane], q1 = rp[32 + lane];

            float x[16];
            {
                float2 p;
                p = __half22float2(*(const __half2*)&q0.x); x[0]=p.x;  x[1]=p.y;
                p = __half22float2(*(const __half2*)&q0.y); x[2]=p.x;  x[3]=p.y;
                p = __half22float2(*(const __half2*)&q0.z); x[4]=p.x;  x[5]=p.y;
                p = __half22float2(*(const __half2*)&q0.w); x[6]=p.x;  x[7]=p.y;
                p = __half22float2(*(const __half2*)&q1.x); x[8]=p.x;  x[9]=p.y;
                p = __half22float2(*(const __half2*)&q1.y); x[10]=p.x; x[11]=p.y;
                p = __half22float2(*(const __half2*)&q1.z); x[12]=p.x; x[13]=p.y;
                p = __half22float2(*(const __half2*)&q1.w); x[14]=p.x; x[15]=p.y;
            }

            float dot = 0.f;
#pragma unroll
            for (int k = 0; k < 16; k++) dot = __fmaf_rn(x[k], sv[k], dot);
#pragma unroll
            for (int o = 16; o; o >>= 1) dot += __shfl_xor_sync(0xFFFFFFFFu, dot, o);

            float uhp;
            if (it == 0) {
                // unscaled denominator: dot*sc + Mmask (overflow-proof)
                float den = __fmaf_rn(dot, scr[r], mmask);
                uhp = __fdividef(ahr[r] * scr[r], fmaxf(den, 1e-35f));
            } else {
                uhp = __fdividef(ahr[r], fmaxf(dot, 1e-35f));
            }

            if (it == NITERS - 1 && lane == 0)
                g_uhat[batch * 512 + row_base + row] = uhp;

#pragma unroll
            for (int k = 0; k < 16; k++) c[k] = __fmaf_rn(x[k], uhp, c[k]);
        }

        // per-warp column partials -> smem
        float4* cp = (float4*)(cpart + w * 512);
        cp[lane * 2]      = make_float4(c[0],  c[1],  c[2],  c[3]);
        cp[lane * 2 + 1]  = make_float4(c[4],  c[5],  c[6],  c[7]);
        cp[64 + lane * 2] = make_float4(c[8],  c[9],  c[10], c[11]);
        cp[65 + lane * 2] = make_float4(c[12], c[13], c[14], c[15]);
        __syncthreads();

        if (t < 512) {
            float s = 0.f;
#pragma unroll
            for (int w2 = 0; w2 < 32; w2++) s += cpart[w2 * 512 + t];
            g_Spart[(it + 1) & 1][batch][slot][t] = s;
        }

        if (it < NITERS - 1) gsync_batch(batch, (unsigned)(it + 1));
    }
}

// ---------------------------------------------------------------------------
// finalA: ot partials. flow = uhat * fp16(t) * ev  (identical t expression as
// tile build -> self-consistent).  grid=(8,B), block=256
__global__ void finalA_kernel(const float* __restrict__ pc_a,
                              const float* __restrict__ pc_b)
{
    __shared__ float ev[512], bxs[512], bys[512];
    __shared__ float red[8];
    int b = blockIdx.y, slot = blockIdx.x;
    int t = threadIdx.x, w = t >> 5, lane = t & 31;

    for (int j = t; j < 512; j += 256) {
        float S = g_Spart[0][b][0][j] + g_Spart[0][b][1][j]
                + g_Spart[0][b][2][j] + g_Spart[0][b][3][j];
        ev[j]  = g_bhat[b * 512 + j] / fmaxf(S, 1e-35f);
        bxs[j] = pc_b[(b * 512 + j) * 3 + 0];
        bys[j] = pc_b[(b * 512 + j) * 3 + 1];
    }
    __syncthreads();

    float acc = 0.f;
    for (int r = 0; r < 64; r++) {
        int g = b * 512 + slot * 64 + r;
        float uh = g_uhat[g];                    // broadcast, warp-uniform
        if (uh != 0.f) {
            float ax = pc_a[g * 3 + 0], ay = pc_a[g * 3 + 1];
            float dm = g_dmin[g];
#pragma unroll
            for (int h = 0; h < 2; h++) {
                int j = h * 256 + t;
                float dx = ax - bxs[j], dy = ay - bys[j];
                float d  = sqrtf(__fmaf_rn(dx, dx, __fmaf_rn(dy, dy, 1e-12f)));
                float arg = fminf((dm - d) * INV_EPS, 0.f) + SHIFT;
                float tq  = __half2float(__float2half(__expf(arg)));
                acc = __fmaf_rn(d * d, (uh * tq) * ev[j], acc);
            }
        }
    }

#pragma unroll
    for (int o = 16; o; o >>= 1) acc += __shfl_xor_sync(0xFFFFFFFFu, acc, o);
    if (lane == 0) red[w] = acc;
    __syncthreads();
    if (t == 0) {
        float s = 0.f;
#pragma unroll
        for (int k = 0; k < 8; k++) s += red[k];
        g_fpart[b * 8 + slot] = s;
    }
}

// finalB: out[b] += sum of 8 partials (acc already carries d^2)
__global__ void finalB_kernel(float* __restrict__ out)
{
    int b = blockIdx.x;
    if (threadIdx.x == 0) {
        float s = 0.f;
#pragma unroll
        for (int k = 0; k < 8; k++) s += g_fpart[b * 8 + k];
        out[b] += s;
    }
}

// ---------------------------------------------------------------------------
extern "C" void kernel_launch(void* const* d_in, const int* in_sizes, int n_in,
                              void* d_out, int out_size)
{
    const float* a_mask = (const float*)d_in[0];
    const float* pc_a   = (const float*)d_in[1];
    const float* b_mask = (const float*)d_in[2];
    const float* pc_b   = (const float*)d_in[3];
    float* out = (float*)d_out;

    static const int SMEM_BYTES = (512 + 32 * 512) * 4 + 128 * 512 * 2;  // 194 KB
    cudaFuncSetAttribute(sinkhorn_kernel,
                         cudaFuncAttributeMaxDynamicSharedMemorySize, SMEM_BYTES);

    prep_kernel<<<Bb, 512>>>(a_mask, pc_a, b_mask, pc_b, out);
    sinkhorn_kernel<<<NBLK, NTHR, SMEM_BYTES>>>(pc_a, pc_b);
    finalA_kernel<<<dim3(8, Bb), 256>>>(pc_a, pc_b);
    finalB_kernel<<<Bb, 32>>>(out);
}

// round 11
// speedup vs baseline: 1.5656x; 1.5656x over previous
#include <cuda_runtime.h>
#include <cuda_fp16.h>
#include <math.h>

#define Bb 32
#define Nn 512
#define Mm 512
#define EPSV 0.05f
#define INV_EPS 20.0f
#define SHIFT 10.0f
#define NITERS 50

#define NBLK 128            // 4 blocks per batch = 1 cluster per batch
#define NTHR 512            // 16 warps, warp owns 8 rows

// Scratch (device globals: allocation-free per harness rules)
__device__ float g_ahat[Bb * Nn];               // normalized masked weights
__device__ float g_bhat[Bb * Mm];
__device__ float g_uhat[Bb * Nn];               // final scaled u'
__device__ float g_ev  [Bb * Mm];               // final ev (for finalA)
__device__ float g_dmin[Bb * Nn];               // per-row min valid distance
__device__ float g_mmask[Bb];                   // # masked columns per batch

// ---------------------------------------------------------------------------
__device__ __forceinline__ unsigned smem_u32(const void* p) {
    unsigned a;
    asm("{ .reg .u64 t; cvta.to.shared.u64 t, %1; cvt.u32.u64 %0, t; }"
        : "=r"(a) : "l"(p));
    return a;
}
__device__ __forceinline__ unsigned mapa_rank(unsigned addr, int rank) {
    unsigned r;
    asm("mapa.shared::cluster.u32 %0, %1, %2;" : "=r"(r) : "r"(addr), "r"(rank));
    return r;
}
__device__ __forceinline__ void st_cluster_f32(unsigned addr, float v) {
    asm volatile("st.shared::cluster.f32 [%0], %1;" :: "r"(addr), "f"(v));
}
#define CLUSTER_SYNC() do { \
    asm volatile("barrier.cluster.arrive.aligned;" ::: "memory"); \
    asm volatile("barrier.cluster.wait.aligned;"   ::: "memory"); \
} while (0)

// ---------------------------------------------------------------------------
// prep: normalized weights, masked-col count, huber into out[b]
__global__ void prep_kernel(const float* __restrict__ a_mask,
                            const float* __restrict__ pc_a,
                            const float* __restrict__ b_mask,
                            const float* __restrict__ pc_b,
                            float* __restrict__ out)
{
    int b = blockIdx.x, t = threadIdx.x;

    float apt = a_mask[b * Nn + t] * pc_a[(b * Nn + t) * 3 + 2];
    float bpt = b_mask[b * Mm + t] * pc_b[(b * Mm + t) * 3 + 2];

    __shared__ float ra[512], rb[512];
    ra[t] = apt; rb[t] = bpt;
    __syncthreads();
    for (int o = 256; o; o >>= 1) {
        if (t < o) { ra[t] += ra[t + o]; rb[t] += rb[t + o]; }
        __syncthreads();
    }
    float sa = ra[0], sb = rb[0];
    __syncthreads();

    g_ahat[b * Nn + t] = apt / sa;   // masked -> 0
    g_bhat[b * Mm + t] = bpt / sb;

    ra[t] = (bpt > 0.f) ? 0.f : 1.f;   // count masked b columns
    __syncthreads();
    for (int o = 256; o; o >>= 1) {
        if (t < o) ra[t] += ra[t + o];
        __syncthreads();
    }
    if (t == 0) {
        g_mmask[b] = ra[0];
        float e = sa - sb;
        float ae = fabsf(e);
        out[b] = (ae <= 1.f) ? 0.5f * e * e : (ae - 0.5f);
    }
}

// ---------------------------------------------------------------------------
// persistent fused Sinkhorn, SMEM tile + cluster-DSMEM column exchange.
// cluster(4): 4 CTAs = 4 row-slots of one batch.
// smem: ev[512] | cpart[16*512] | inbox[2][4][512] | tile half[128*512]
__global__ void __launch_bounds__(NTHR, 1) __cluster_dims__(4, 1, 1)
sinkhorn_kernel(const float* __restrict__ pc_a, const float* __restrict__ pc_b)
{
    extern __shared__ float smem[];
    float*  ev    = smem;                         // 512
    float*  cpart = smem + 512;                   // 16*512
    float*  inbox = smem + 512 + 16 * 512;        // 2*4*512
    __half* tile  = (__half*)(smem + 512 + 16 * 512 + 8 * 512); // 128*512 h

    int batch    = blockIdx.x >> 2;
    int slot     = blockIdx.x & 3;
    int row_base = slot * 128;
    int t = threadIdx.x, w = t >> 5, lane = t & 31;

    // ---- build tile ---- (temporary overlay of pc_b columns in cpart space)
    float* bxs = cpart;
    float* bys = cpart + 512;
    float* bvs = cpart + 1024;
    for (int j = t; j < 512; j += NTHR) {
        int gb = batch * 512 + j;
        bxs[j] = pc_b[gb * 3 + 0];
        bys[j] = pc_b[gb * 3 + 1];
        bvs[j] = g_bhat[gb];                    // >0 iff valid column
    }
    __syncthreads();

    float mmask = g_mmask[batch];
    float scr[8], ahr[8];
#pragma unroll
    for (int r = 0; r < 8; r++) {
        int row  = w * 8 + r;
        int grow = batch * 512 + row_base + row;
        float ax = pc_a[grow * 3 + 0];          // broadcast
        float ay = pc_a[grow * 3 + 1];
        float ah = g_ahat[grow];
        ahr[r] = ah;

        float dv[16];
        float mn = 1e30f;
#pragma unroll
        for (int k = 0; k < 16; k++) {
            int j = k * 32 + lane;
            float dx = ax - bxs[j], dy = ay - bys[j];
            float d  = sqrtf(__fmaf_rn(dx, dx, __fmaf_rn(dy, dy, 1e-12f)));
            dv[k] = d;
            if (bvs[j] > 0.f) mn = fminf(mn, d);
        }
#pragma unroll
        for (int o = 16; o; o >>= 1) mn = fminf(mn, __shfl_xor_sync(0xFFFFFFFFu, mn, o));

        if (lane == 0) g_dmin[grow] = mn;
        scr[r] = __expf(-__fmaf_rn(INV_EPS, mn, SHIFT));   // e^{-20*mn-SHIFT}

#pragma unroll
        for (int k = 0; k < 16; k++) {
            int j = k * 32 + lane;
            float arg = fminf((mn - dv[k]) * INV_EPS, 0.f) + SHIFT;
            float tv  = (bvs[j] > 0.f && ah > 0.f) ? __expf(arg) : 0.f;
            tile[row * 512 + j] = __float2half(tv);
        }
    }

    float bh = g_bhat[batch * 512 + t];
    __syncthreads();     // cpart overlay dead

    // precompute this thread's inbox slot addresses in all 4 cluster CTAs
    unsigned my0 = smem_u32(&inbox[(size_t)slot * 512 + t]);            // buf 0
    unsigned my1 = my0 + 4u * 2048u;                                    // buf 1
    unsigned pa0[4], pa1[4];
#pragma unroll
    for (int rk = 0; rk < 4; rk++) {
        pa0[rk] = mapa_rank(my0, rk);
        pa1[rk] = mapa_rank(my1, rk);
    }

    // mbarrier-free: inboxes only written after cluster barriers below.
    CLUSTER_SYNC();      // all CTAs' smem laid out before any DSMEM store

    int buf = 0;
    // ---- 50 iterations ----
    for (int it = 0; it < NITERS; ++it) {
        if (it == 0) {
            ev[t] = 1.f;                        // reference: logv starts at 0
        } else {
            const float* ib = inbox + (size_t)buf * 2048;
            float S = ib[t] + ib[512 + t] + ib[1024 + t] + ib[1536 + t];
            ev[t] = bh / fmaxf(S, 1e-35f);      // masked: bh=0 -> ev=0
        }
        __syncthreads();

        const float4* ev4 = (const float4*)ev;
        float4 e0 = ev4[lane * 2],      e1 = ev4[lane * 2 + 1];
        float4 e2 = ev4[64 + lane * 2], e3 = ev4[64 + lane * 2 + 1];
        float sv[16] = {e0.x,e0.y,e0.z,e0.w, e1.x,e1.y,e1.z,e1.w,
                        e2.x,e2.y,e2.z,e2.w, e3.x,e3.y,e3.z,e3.w};

        float c[16];
#pragma unroll
        for (int k = 0; k < 16; k++) c[k] = 0.f;

#pragma unroll
        for (int r = 0; r < 8; r++) {
            int row = w * 8 + r;
            const uint4* rp = (const uint4*)(tile + row * 512);
            uint4 q0 = rp[lane], q1 = rp[32 + lane];

            float x[16];
            {
                float2 p;
                p = __half22float2(*(const __half2*)&q0.x); x[0]=p.x;  x[1]=p.y;
                p = __half22float2(*(const __half2*)&q0.y); x[2]=p.x;  x[3]=p.y;
                p = __half22float2(*(const __half2*)&q0.z); x[4]=p.x;  x[5]=p.y;
                p = __half22float2(*(const __half2*)&q0.w); x[6]=p.x;  x[7]=p.y;
                p = __half22float2(*(const __half2*)&q1.x); x[8]=p.x;  x[9]=p.y;
                p = __half22float2(*(const __half2*)&q1.y); x[10]=p.x; x[11]=p.y;
                p = __half22float2(*(const __half2*)&q1.z); x[12]=p.x; x[13]=p.y;
                p = __half22float2(*(const __half2*)&q1.w); x[14]=p.x; x[15]=p.y;
            }

            float dot = 0.f;
#pragma unroll
            for (int k = 0; k < 16; k++) dot = __fmaf_rn(x[k], sv[k], dot);
#pragma unroll
            for (int o = 16; o; o >>= 1) dot += __shfl_xor_sync(0xFFFFFFFFu, dot, o);

            float uhp;
            if (it == 0) {
                float den = __fmaf_rn(dot, scr[r], mmask);   // overflow-proof
                uhp = __fdividef(ahr[r] * scr[r], fmaxf(den, 1e-35f));
            } else {
                uhp = __fdividef(ahr[r], fmaxf(dot, 1e-35f));
            }

            if (it == NITERS - 1 && lane == 0)
                g_uhat[batch * 512 + row_base + row] = uhp;

#pragma unroll
            for (int k = 0; k < 16; k++) c[k] = __fmaf_rn(x[k], uhp, c[k]);
        }

        // per-warp column partials -> smem
        float4* cp = (float4*)(cpart + w * 512);
        cp[lane * 2]      = make_float4(c[0],  c[1],  c[2],  c[3]);
        cp[lane * 2 + 1]  = make_float4(c[4],  c[5],  c[6],  c[7]);
        cp[64 + lane * 2] = make_float4(c[8],  c[9],  c[10], c[11]);
        cp[65 + lane * 2] = make_float4(c[12], c[13], c[14], c[15]);
        __syncthreads();

        float s = 0.f;
#pragma unroll
        for (int w2 = 0; w2 < 16; w2++) s += cpart[w2 * 512 + t];

        // broadcast partial into all 4 cluster CTAs' inbox[buf^1][slot][t]
        const unsigned* pa = buf ? pa0 : pa1;
#pragma unroll
        for (int rk = 0; rk < 4; rk++) st_cluster_f32(pa[rk], s);

        CLUSTER_SYNC();          // release stores, acquire for next read
        buf ^= 1;
    }

    // final ev for the flow (slot 0 writes)
    if (slot == 0) {
        const float* ib = inbox + (size_t)buf * 2048;
        float S = ib[t] + ib[512 + t] + ib[1024 + t] + ib[1536 + t];
        g_ev[batch * 512 + t] = bh / fmaxf(S, 1e-35f);
    }
    CLUSTER_SYNC();              // no CTA exits while peers may still read
}

// ---------------------------------------------------------------------------
// finalA: ot partials, atomicAdd into out[b]. flow = uhat * fp16(t) * ev.
// grid=(8,B), block=256
__global__ void finalA_kernel(const float* __restrict__ pc_a,
                              const float* __restrict__ pc_b,
                              float* __restrict__ out)
{
    __shared__ float ev[512], bxs[512], bys[512];
    __shared__ float red[8];
    int b = blockIdx.y, slot = blockIdx.x;
    int t = threadIdx.x, w = t >> 5, lane = t & 31;

    for (int j = t; j < 512; j += 256) {
        ev[j]  = g_ev[b * 512 + j];
        bxs[j] = pc_b[(b * 512 + j) * 3 + 0];
        bys[j] = pc_b[(b * 512 + j) * 3 + 1];
    }
    __syncthreads();

    float acc = 0.f;
    for (int r = 0; r < 64; r++) {
        int g = b * 512 + slot * 64 + r;
        float uh = g_uhat[g];                    // broadcast, warp-uniform
        if (uh != 0.f) {
            float ax = pc_a[g * 3 + 0], ay = pc_a[g * 3 + 1];
            float dm = g_dmin[g];
#pragma unroll
            for (int h = 0; h < 2; h++) {
                int j = h * 256 + t;
                float dx = ax - bxs[j], dy = ay - bys[j];
                float d  = sqrtf(__fmaf_rn(dx, dx, __fmaf_rn(dy, dy, 1e-12f)));
                float arg = fminf((dm - d) * INV_EPS, 0.f) + SHIFT;
                float tq  = __half2float(__float2half(__expf(arg)));
                acc = __fmaf_rn(d * d, (uh * tq) * ev[j], acc);
            }
        }
    }

#pragma unroll
    for (int o = 16; o; o >>= 1) acc += __shfl_xor_sync(0xFFFFFFFFu, acc, o);
    if (lane == 0) red[w] = acc;
    __syncthreads();
    if (t == 0) {
        float s = 0.f;
#pragma unroll
        for (int k = 0; k < 8; k++) s += red[k];
        atomicAdd(&out[b], s);
    }
}

// ---------------------------------------------------------------------------
extern "C" void kernel_launch(void* const* d_in, const int* in_sizes, int n_in,
                              void* d_out, int out_size)
{
    const float* a_mask = (const float*)d_in[0];
    const float* pc_a   = (const float*)d_in[1];
    const float* b_mask = (const float*)d_in[2];
    const float* pc_b   = (const float*)d_in[3];
    float* out = (float*)d_out;

    // ev + cpart + inbox(2x4x512) + tile
    static const int SMEM_BYTES =
        (512 + 16 * 512 + 8 * 512) * 4 + 128 * 512 * 2;   // 178 KB
    cudaFuncSetAttribute(sinkhorn_kernel,
                         cudaFuncAttributeMaxDynamicSharedMemorySize, SMEM_BYTES);

    prep_kernel<<<Bb, 512>>>(a_mask, pc_a, b_mask, pc_b, out);
    sinkhorn_kernel<<<NBLK, NTHR, SMEM_BYTES>>>(pc_a, pc_b);
    finalA_kernel<<<dim3(8, Bb), 256>>>(pc_a, pc_b, out);
}